// round 1
// baseline (speedup 1.0000x reference)
#include <cuda_runtime.h>

// CompositeBezierCurve: out[n,3] = sum_k C(7,k) s^k (1-s)^(7-k) * cp[idx,k,:]
// where idx = floor(mod(x,10000)), s = frac. Knots are uniform integers so the
// searchsorted collapses to floor().
//
// Inputs (metadata order):
//   d_in[0] = x_eval          float32 [4194304]
//   d_in[1] = knots_x         float32 [10001]   (unused: uniform integer knots)
//   d_in[2] = control_points  float32 [10000,8,3]
// Output: float32 [4194304,3]

#define NUM_SEG   10000
#define PTS_PER_THREAD 4

__global__ __launch_bounds__(256)
void bezier_eval_kernel(const float4* __restrict__ x4,
                        const float4* __restrict__ cp4,   // control_points as float4 (6 per segment)
                        float4* __restrict__ out4,        // output as float4 (3 per 4 points)
                        int n4)                           // number of 4-point groups
{
    int g = blockIdx.x * blockDim.x + threadIdx.x;
    if (g >= n4) return;

    float4 xv = __ldg(&x4[g]);
    const float xs[4] = {xv.x, xv.y, xv.z, xv.w};

    float acc[12];  // 4 points x 3 dims

    #pragma unroll
    for (int p = 0; p < 4; p++) {
        float x = xs[p];
        // x_true = mod(x, 10000); inputs are in [0,10000) but keep it exact
        float xt = x - 10000.0f * floorf(x * (1.0f / 10000.0f));
        int idx = (int)floorf(xt);
        idx = max(0, min(idx, NUM_SEG - 1));
        float s = xt - (float)idx;
        float u = 1.0f - s;

        // Bernstein weights for degree 7: C(7,k) s^k u^(7-k)
        float s2 = s * s, s3 = s2 * s, s4 = s2 * s2, s5 = s4 * s, s6 = s3 * s3, s7 = s6 * s;
        float u2 = u * u, u3 = u2 * u, u4 = u2 * u2, u5 = u4 * u, u6 = u3 * u3, u7 = u6 * u;
        float w0 = u7;
        float w1 = 7.0f  * s  * u6;
        float w2 = 21.0f * s2 * u5;
        float w3 = 35.0f * s3 * u4;
        float w4 = 35.0f * s4 * u3;
        float w5 = 21.0f * s5 * u2;
        float w6 = 7.0f  * s6 * u;
        float w7 = s7;

        // Gather this segment's 8x3 control points: 6 x float4 = 24 floats
        const float4* seg = cp4 + (size_t)idx * 6;
        float4 c0 = __ldg(&seg[0]);
        float4 c1 = __ldg(&seg[1]);
        float4 c2 = __ldg(&seg[2]);
        float4 c3 = __ldg(&seg[3]);
        float4 c4 = __ldg(&seg[4]);
        float4 c5 = __ldg(&seg[5]);
        // layout: f[3k+d]; unpack
        // k0:(c0.x,c0.y,c0.z) k1:(c0.w,c1.x,c1.y) k2:(c1.z,c1.w,c2.x) k3:(c2.y,c2.z,c2.w)
        // k4:(c3.x,c3.y,c3.z) k5:(c3.w,c4.x,c4.y) k6:(c4.z,c4.w,c5.x) k7:(c5.y,c5.z,c5.w)
        float ox, oy, oz;
        ox = w0 * c0.x; oy = w0 * c0.y; oz = w0 * c0.z;
        ox = fmaf(w1, c0.w, ox); oy = fmaf(w1, c1.x, oy); oz = fmaf(w1, c1.y, oz);
        ox = fmaf(w2, c1.z, ox); oy = fmaf(w2, c1.w, oy); oz = fmaf(w2, c2.x, oz);
        ox = fmaf(w3, c2.y, ox); oy = fmaf(w3, c2.z, oy); oz = fmaf(w3, c2.w, oz);
        ox = fmaf(w4, c3.x, ox); oy = fmaf(w4, c3.y, oy); oz = fmaf(w4, c3.z, oz);
        ox = fmaf(w5, c3.w, ox); oy = fmaf(w5, c4.x, oy); oz = fmaf(w5, c4.y, oz);
        ox = fmaf(w6, c4.z, ox); oy = fmaf(w6, c4.w, oy); oz = fmaf(w6, c5.x, oz);
        ox = fmaf(w7, c5.y, ox); oy = fmaf(w7, c5.z, oy); oz = fmaf(w7, c5.w, oz);

        acc[3 * p + 0] = ox;
        acc[3 * p + 1] = oy;
        acc[3 * p + 2] = oz;
    }

    // 12 contiguous floats per group -> 3 float4 stores, 16B aligned (48B stride)
    float4* o = out4 + (size_t)g * 3;
    o[0] = make_float4(acc[0], acc[1], acc[2],  acc[3]);
    o[1] = make_float4(acc[4], acc[5], acc[6],  acc[7]);
    o[2] = make_float4(acc[8], acc[9], acc[10], acc[11]);
}

extern "C" void kernel_launch(void* const* d_in, const int* in_sizes, int n_in,
                              void* d_out, int out_size)
{
    const float* x_eval = (const float*)d_in[0];
    // d_in[1] = knots_x (unused: uniform integer knots)
    const float* cp     = (const float*)d_in[2];
    float* out          = (float*)d_out;

    int n  = in_sizes[0];          // 4194304
    int n4 = n / 4;                // divisible by 4

    int threads = 256;
    int blocks  = (n4 + threads - 1) / threads;
    bezier_eval_kernel<<<blocks, threads>>>(
        (const float4*)x_eval, (const float4*)cp, (float4*)out, n4);
}

// round 2
// speedup vs baseline: 1.0217x; 1.0217x over previous
#include <cuda_runtime.h>

// CompositeBezierCurve on GB300 — smem-staged coalesced gather.
//
// out[n,3] = sum_k C(7,k) s^k (1-s)^(7-k) * cp[idx,k,:]
// idx = floor(mod(x,10000)), s = frac (knots are exact uniform integers).
//
// Inputs (metadata order):
//   d_in[0] = x_eval          float32 [4194304]
//   d_in[1] = knots_x         float32 [10001]   (unused: uniform integer knots)
//   d_in[2] = control_points  float32 [10000,8,3]
// Output: float32 [4194304,3]

#define NSEG 10000
#define TPB  256

__global__ __launch_bounds__(TPB)
void bezier_eval_staged(const float* __restrict__ x_eval,
                        const float4* __restrict__ cp4,   // 6 float4 per segment
                        float* __restrict__ out,
                        int n)
{
    __shared__ int   s_idx[TPB];
    __shared__ float s_cp[TPB][28];   // 24 data floats + 4 pad (112B row, 16B aligned)

    const int tid = threadIdx.x;
    const int g   = blockIdx.x * TPB + tid;

    // ---- phase 1: per-point segment index ----
    float xt = 0.0f;
    int   idx = 0;
    if (g < n) {
        float x = x_eval[g];
        // x_true = mod(x, 10000)
        xt  = x - 10000.0f * floorf(x * 1e-4f);
        idx = (int)floorf(xt);
        idx = max(0, min(idx, NSEG - 1));
    }
    s_idx[tid] = idx;
    __syncthreads();

    // ---- phase 2: cooperative coalesced gather ----
    // 256 points * 6 float4 = 1536 loads; consecutive threads take consecutive
    // 16B chunks of the same segment -> each segment's 96B spans <=2 cache
    // lines -> ~1.5 L1 wavefronts per point instead of 6.
    #pragma unroll
    for (int r = 0; r < 6; r++) {
        int l = r * TPB + tid;
        int p = l / 6;            // point within block
        int j = l - p * 6;        // float4 chunk within segment
        int seg = s_idx[p];
        float4 v = __ldg(&cp4[(size_t)seg * 6 + j]);
        *reinterpret_cast<float4*>(&s_cp[p][4 * j]) = v;
    }
    __syncthreads();

    if (g >= n) return;

    // ---- phase 3: Bernstein weights + dot product from smem ----
    float s = xt - (float)idx;
    float u = 1.0f - s;

    float s2 = s * s, s3 = s2 * s, s4 = s2 * s2, s5 = s4 * s, s6 = s3 * s3, s7 = s6 * s;
    float u2 = u * u, u3 = u2 * u, u4 = u2 * u2, u5 = u4 * u, u6 = u3 * u3, u7 = u6 * u;
    float w0 = u7;
    float w1 = 7.0f  * s  * u6;
    float w2 = 21.0f * s2 * u5;
    float w3 = 35.0f * s3 * u4;
    float w4 = 35.0f * s4 * u3;
    float w5 = 21.0f * s5 * u2;
    float w6 = 7.0f  * s6 * u;
    float w7 = s7;

    // conflict-free LDS.128: word index 28*tid + 4*j distinct mod 32 per phase
    float4 c0 = *reinterpret_cast<const float4*>(&s_cp[tid][0]);
    float4 c1 = *reinterpret_cast<const float4*>(&s_cp[tid][4]);
    float4 c2 = *reinterpret_cast<const float4*>(&s_cp[tid][8]);
    float4 c3 = *reinterpret_cast<const float4*>(&s_cp[tid][12]);
    float4 c4 = *reinterpret_cast<const float4*>(&s_cp[tid][16]);
    float4 c5 = *reinterpret_cast<const float4*>(&s_cp[tid][20]);

    // layout per segment: floats f[3k+d]
    // k0:(c0.x,c0.y,c0.z) k1:(c0.w,c1.x,c1.y) k2:(c1.z,c1.w,c2.x) k3:(c2.y,c2.z,c2.w)
    // k4:(c3.x,c3.y,c3.z) k5:(c3.w,c4.x,c4.y) k6:(c4.z,c4.w,c5.x) k7:(c5.y,c5.z,c5.w)
    float ox, oy, oz;
    ox = w0 * c0.x;          oy = w0 * c0.y;          oz = w0 * c0.z;
    ox = fmaf(w1, c0.w, ox); oy = fmaf(w1, c1.x, oy); oz = fmaf(w1, c1.y, oz);
    ox = fmaf(w2, c1.z, ox); oy = fmaf(w2, c1.w, oy); oz = fmaf(w2, c2.x, oz);
    ox = fmaf(w3, c2.y, ox); oy = fmaf(w3, c2.z, oy); oz = fmaf(w3, c2.w, oz);
    ox = fmaf(w4, c3.x, ox); oy = fmaf(w4, c3.y, oy); oz = fmaf(w4, c3.z, oz);
    ox = fmaf(w5, c3.w, ox); oy = fmaf(w5, c4.x, oy); oz = fmaf(w5, c4.y, oz);
    ox = fmaf(w6, c4.z, ox); oy = fmaf(w6, c4.w, oy); oz = fmaf(w6, c5.x, oz);
    ox = fmaf(w7, c5.y, ox); oy = fmaf(w7, c5.z, oy); oz = fmaf(w7, c5.w, oz);

    out[3 * (size_t)g + 0] = ox;
    out[3 * (size_t)g + 1] = oy;
    out[3 * (size_t)g + 2] = oz;
}

extern "C" void kernel_launch(void* const* d_in, const int* in_sizes, int n_in,
                              void* d_out, int out_size)
{
    const float* x_eval = (const float*)d_in[0];
    // d_in[1] = knots_x (unused: uniform integer knots)
    const float* cp     = (const float*)d_in[2];
    float* out          = (float*)d_out;

    int n = in_sizes[0];                 // 4194304
    int blocks = (n + TPB - 1) / TPB;    // 16384

    bezier_eval_staged<<<blocks, TPB>>>(x_eval, (const float4*)cp, out, n);
}

// round 3
// speedup vs baseline: 1.0720x; 1.0493x over previous
#include <cuda_runtime.h>

// CompositeBezierCurve on GB300 — padded-line gather + conflict-free staging.
//
// out[n,3] = sum_k C(7,k) s^k (1-s)^(7-k) * cp[idx,k,:]
// idx = floor(mod(x,10000)), s = frac (knots are exact uniform integers).
//
// Inputs (metadata order):
//   d_in[0] = x_eval          float32 [4194304]
//   d_in[1] = knots_x         float32 [10001]   (unused: uniform integer knots)
//   d_in[2] = control_points  float32 [10000,8,3]
// Output: float32 [4194304,3]

#define NSEG 10000
#define TPB  256

// Padded control-point table: 8 float4 (128B, one cache line) per segment.
// Chunks 0..5 hold the 24 floats; 6..7 are never written/read.
__device__ float4 g_cp_pad[NSEG * 8];

__global__ void pad_cp_kernel(const float4* __restrict__ cp4)
{
    int i = blockIdx.x * blockDim.x + threadIdx.x;   // chunk id, 60000 total
    if (i < NSEG * 6) {
        int seg = i / 6;
        int j   = i - 6 * seg;
        g_cp_pad[seg * 8 + j] = __ldg(&cp4[i]);
    }
}

__global__ __launch_bounds__(TPB)
void bezier_eval_padded(const float* __restrict__ x_eval,
                        float* __restrict__ out,
                        int n)
{
    __shared__ int   s_idx[TPB];
    __shared__ float s_cp[TPB * 36];   // 36-float rows: STS & LDS both bank-conflict-free

    const int tid = threadIdx.x;
    const int g   = blockIdx.x * TPB + tid;

    // ---- phase 1: per-point segment index ----
    float xt = 0.0f;
    int   idx = 0;
    if (g < n) {
        float x = x_eval[g];
        xt  = x - 10000.0f * floorf(x * 1e-4f);      // mod(x, 10000)
        idx = (int)floorf(xt);
        idx = max(0, min(idx, NSEG - 1));
    }
    s_idx[tid] = idx;
    __syncthreads();

    // ---- phase 2: cooperative gather, 8 lanes per point ----
    // l = 8p + j: each warp instruction reads exactly 4 aligned 128B lines
    // (4 wavefronts, 100% line efficiency). Lanes j=6,7 are predicated off;
    // their sectors are never fetched, so L2 traffic is unchanged.
    #pragma unroll
    for (int r = 0; r < 8; r++) {
        int l = r * TPB + tid;
        int p = l >> 3;
        int j = l & 7;
        if (j < 6) {
            int seg = s_idx[p];                       // 8-lane broadcast, conflict-free
            float4 v = __ldg(&g_cp_pad[seg * 8 + j]);
            // STS banks: (36p + 4j) mod 32 = 4p+4j, distinct over j in each
            // 8-lane quarter (one point per quarter) -> conflict-free.
            *reinterpret_cast<float4*>(&s_cp[p * 36 + 4 * j]) = v;
        }
    }
    __syncthreads();

    if (g >= n) return;

    // ---- phase 3: Bernstein weights + dot product ----
    float s = xt - (float)idx;
    float u = 1.0f - s;

    float s2 = s * s, s3 = s2 * s, s4 = s2 * s2, s5 = s4 * s, s6 = s3 * s3, s7 = s6 * s;
    float u2 = u * u, u3 = u2 * u, u4 = u2 * u2, u5 = u4 * u, u6 = u3 * u3, u7 = u6 * u;
    float w0 = u7;
    float w1 = 7.0f  * s  * u6;
    float w2 = 21.0f * s2 * u5;
    float w3 = 35.0f * s3 * u4;
    float w4 = 35.0f * s4 * u3;
    float w5 = 21.0f * s5 * u2;
    float w6 = 7.0f  * s6 * u;
    float w7 = s7;

    // LDS banks: (36t + 4j) mod 32 = 4t+4j, distinct over t in each 8-lane
    // phase (j fixed per instruction) -> conflict-free LDS.128.
    const float* c = &s_cp[tid * 36];
    float4 c0 = *reinterpret_cast<const float4*>(c + 0);
    float4 c1 = *reinterpret_cast<const float4*>(c + 4);
    float4 c2 = *reinterpret_cast<const float4*>(c + 8);
    float4 c3 = *reinterpret_cast<const float4*>(c + 12);
    float4 c4 = *reinterpret_cast<const float4*>(c + 16);
    float4 c5 = *reinterpret_cast<const float4*>(c + 20);

    // per-segment float layout f[3k+d]:
    // k0:(c0.x,c0.y,c0.z) k1:(c0.w,c1.x,c1.y) k2:(c1.z,c1.w,c2.x) k3:(c2.y,c2.z,c2.w)
    // k4:(c3.x,c3.y,c3.z) k5:(c3.w,c4.x,c4.y) k6:(c4.z,c4.w,c5.x) k7:(c5.y,c5.z,c5.w)
    float ox, oy, oz;
    ox = w0 * c0.x;          oy = w0 * c0.y;          oz = w0 * c0.z;
    ox = fmaf(w1, c0.w, ox); oy = fmaf(w1, c1.x, oy); oz = fmaf(w1, c1.y, oz);
    ox = fmaf(w2, c1.z, ox); oy = fmaf(w2, c1.w, oy); oz = fmaf(w2, c2.x, oz);
    ox = fmaf(w3, c2.y, ox); oy = fmaf(w3, c2.z, oy); oz = fmaf(w3, c2.w, oz);
    ox = fmaf(w4, c3.x, ox); oy = fmaf(w4, c3.y, oy); oz = fmaf(w4, c3.z, oz);
    ox = fmaf(w5, c3.w, ox); oy = fmaf(w5, c4.x, oy); oz = fmaf(w5, c4.y, oz);
    ox = fmaf(w6, c4.z, ox); oy = fmaf(w6, c4.w, oy); oz = fmaf(w6, c5.x, oz);
    ox = fmaf(w7, c5.y, ox); oy = fmaf(w7, c5.z, oy); oz = fmaf(w7, c5.w, oz);

    out[3 * (size_t)g + 0] = ox;
    out[3 * (size_t)g + 1] = oy;
    out[3 * (size_t)g + 2] = oz;
}

extern "C" void kernel_launch(void* const* d_in, const int* in_sizes, int n_in,
                              void* d_out, int out_size)
{
    const float* x_eval = (const float*)d_in[0];
    // d_in[1] = knots_x (unused: uniform integer knots)
    const float* cp     = (const float*)d_in[2];
    float* out          = (float*)d_out;

    int n = in_sizes[0];                 // 4194304

    // 1) pad control points into one-line-per-segment scratch (same stream,
    //    graph-captured, deterministic)
    int chunks = NSEG * 6;
    pad_cp_kernel<<<(chunks + 255) / 256, 256>>>((const float4*)cp);

    // 2) main eval
    int blocks = (n + TPB - 1) / TPB;    // 16384
    bezier_eval_padded<<<blocks, TPB>>>(x_eval, out, n);
}

// round 4
// speedup vs baseline: 1.2517x; 1.1676x over previous
#include <cuda_runtime.h>

// CompositeBezierCurve on GB300 — direct gather with 256-bit loads.
//
// out[n,3] = sum_k C(7,k) s^k (1-s)^(7-k) * cp[idx,k,:]
// idx = floor(mod(x,10000)), s = frac (knots are exact uniform integers).
//
// Each segment is 96B with base = idx*96 (32B aligned), so three 32B-aligned
// LDG.256 cover it with exactly 3 L1 line-passes per point (32B chunks never
// straddle a 128B line). No smem staging, no barriers, 12 independent loads
// in flight per thread.
//
// Inputs (metadata order):
//   d_in[0] = x_eval          float32 [4194304]
//   d_in[1] = knots_x         float32 [10001]   (unused: uniform integer knots)
//   d_in[2] = control_points  float32 [10000,8,3]
// Output: float32 [4194304,3]

#define NSEG 10000
#define TPB  128

__device__ __forceinline__ void ldg256(const float* __restrict__ p, float* r)
{
    asm("ld.global.nc.v8.f32 {%0,%1,%2,%3,%4,%5,%6,%7}, [%8];"
        : "=f"(r[0]), "=f"(r[1]), "=f"(r[2]), "=f"(r[3]),
          "=f"(r[4]), "=f"(r[5]), "=f"(r[6]), "=f"(r[7])
        : "l"(p));
}

__global__ __launch_bounds__(TPB)
void bezier_eval_v8(const float4* __restrict__ x4,
                    const float* __restrict__ cp,
                    float4* __restrict__ out4,
                    int n4)
{
    int g = blockIdx.x * TPB + threadIdx.x;
    if (g >= n4) return;

    float4 xv = __ldg(&x4[g]);
    const float xs[4] = {xv.x, xv.y, xv.z, xv.w};

    float acc[12];

    #pragma unroll
    for (int p = 0; p < 4; p++) {
        float x  = xs[p];
        float xt = x - 10000.0f * floorf(x * 1e-4f);   // mod(x, 10000)
        int idx  = (int)floorf(xt);
        idx = max(0, min(idx, NSEG - 1));
        float s = xt - (float)idx;
        float u = 1.0f - s;

        // gather 96B = 3 x 256-bit loads, all 32B aligned
        const float* seg = cp + (size_t)idx * 24;
        float a[8], b[8], c[8];
        ldg256(seg +  0, a);
        ldg256(seg +  8, b);
        ldg256(seg + 16, c);

        // Bernstein weights, degree 7
        float s2 = s * s, s3 = s2 * s, s4 = s2 * s2, s5 = s4 * s, s6 = s3 * s3, s7 = s6 * s;
        float u2 = u * u, u3 = u2 * u, u4 = u2 * u2, u5 = u4 * u, u6 = u3 * u3, u7 = u6 * u;
        float w0 = u7;
        float w1 = 7.0f  * s  * u6;
        float w2 = 21.0f * s2 * u5;
        float w3 = 35.0f * s3 * u4;
        float w4 = 35.0f * s4 * u3;
        float w5 = 21.0f * s5 * u2;
        float w6 = 7.0f  * s6 * u;
        float w7 = s7;

        // floats f[3k+d]: a=f0..f7, b=f8..f15, c=f16..f23
        float ox, oy, oz;
        ox = w0 * a[0];          oy = w0 * a[1];          oz = w0 * a[2];
        ox = fmaf(w1, a[3], ox); oy = fmaf(w1, a[4], oy); oz = fmaf(w1, a[5], oz);
        ox = fmaf(w2, a[6], ox); oy = fmaf(w2, a[7], oy); oz = fmaf(w2, b[0], oz);
        ox = fmaf(w3, b[1], ox); oy = fmaf(w3, b[2], oy); oz = fmaf(w3, b[3], oz);
        ox = fmaf(w4, b[4], ox); oy = fmaf(w4, b[5], oy); oz = fmaf(w4, b[6], oz);
        ox = fmaf(w5, b[7], ox); oy = fmaf(w5, c[0], oy); oz = fmaf(w5, c[1], oz);
        ox = fmaf(w6, c[2], ox); oy = fmaf(w6, c[3], oy); oz = fmaf(w6, c[4], oz);
        ox = fmaf(w7, c[5], ox); oy = fmaf(w7, c[6], oy); oz = fmaf(w7, c[7], oz);

        acc[3 * p + 0] = ox;
        acc[3 * p + 1] = oy;
        acc[3 * p + 2] = oz;
    }

    float4* o = out4 + (size_t)g * 3;
    o[0] = make_float4(acc[0], acc[1], acc[2],  acc[3]);
    o[1] = make_float4(acc[4], acc[5], acc[6],  acc[7]);
    o[2] = make_float4(acc[8], acc[9], acc[10], acc[11]);
}

extern "C" void kernel_launch(void* const* d_in, const int* in_sizes, int n_in,
                              void* d_out, int out_size)
{
    const float* x_eval = (const float*)d_in[0];
    // d_in[1] = knots_x (unused: uniform integer knots)
    const float* cp     = (const float*)d_in[2];
    float* out          = (float*)d_out;

    int n  = in_sizes[0];      // 4194304
    int n4 = n / 4;            // 1048576 groups

    int blocks = (n4 + TPB - 1) / TPB;
    bezier_eval_v8<<<blocks, TPB>>>((const float4*)x_eval, cp, (float4*)out, n4);
}